// round 2
// baseline (speedup 1.0000x reference)
#include <cuda_runtime.h>
#include <math.h>

// Problem constants
#define S_LEN   2048
#define D_MODEL 768
#define NH      12
#define DHEAD   64
#define BATCH   2
#define MROWS   (BATCH * S_LEN)   // 4096

// Scratch (device globals: no allocation allowed)
__device__ float g_q[MROWS * D_MODEL];
__device__ float g_k[MROWS * D_MODEL];
__device__ float g_v[MROWS * D_MODEL];
__device__ float g_ctx[MROWS * D_MODEL];

// ---------------------------------------------------------------------------
// Tiled SGEMM with bias: C[M,N] = A[M,K] @ W[K,N] + bias[N]
// BM=BN=64, BK=16, 256 threads, 4x4 register micro-tile per thread.
// ---------------------------------------------------------------------------
#define BM 64
#define BN 64
#define BKK 16

__global__ __launch_bounds__(256) void gemm_bias_kernel(
    const float* __restrict__ A, const float* __restrict__ W,
    const float* __restrict__ bias, float* __restrict__ C,
    int M, int N, int K)
{
    __shared__ float As[BKK][BM + 4];   // transposed: As[k][m]
    __shared__ float Bs[BKK][BN + 4];   // Bs[k][n]

    const int tid = threadIdx.x;
    const int tx = tid & 15;            // 0..15  (n direction)
    const int ty = tid >> 4;            // 0..15  (m direction)

    const int m0 = blockIdx.x * BM;
    const int n0 = blockIdx.y * BN;

    // global-load mapping
    const int arow = tid >> 2;          // 0..63
    const int akg  = (tid & 3) << 2;    // 0,4,8,12  (k)
    const int brow = tid >> 4;          // 0..15     (k)
    const int bcol = (tid & 15) << 2;   // 0..60     (n)

    float acc[4][4] = {};

    for (int k0 = 0; k0 < K; k0 += BKK) {
        // load A tile (transposed into smem)
        float4 a4 = *(const float4*)&A[(size_t)(m0 + arow) * K + k0 + akg];
        As[akg + 0][arow] = a4.x;
        As[akg + 1][arow] = a4.y;
        As[akg + 2][arow] = a4.z;
        As[akg + 3][arow] = a4.w;
        // load W tile
        float4 b4 = *(const float4*)&W[(size_t)(k0 + brow) * N + n0 + bcol];
        *(float4*)&Bs[brow][bcol] = b4;
        __syncthreads();

#pragma unroll
        for (int k = 0; k < BKK; k++) {
            float4 av = *(const float4*)&As[k][ty << 2];
            float4 bv = *(const float4*)&Bs[k][tx << 2];
            acc[0][0] += av.x * bv.x; acc[0][1] += av.x * bv.y;
            acc[0][2] += av.x * bv.z; acc[0][3] += av.x * bv.w;
            acc[1][0] += av.y * bv.x; acc[1][1] += av.y * bv.y;
            acc[1][2] += av.y * bv.z; acc[1][3] += av.y * bv.w;
            acc[2][0] += av.z * bv.x; acc[2][1] += av.z * bv.y;
            acc[2][2] += av.z * bv.z; acc[2][3] += av.z * bv.w;
            acc[3][0] += av.w * bv.x; acc[3][1] += av.w * bv.y;
            acc[3][2] += av.w * bv.z; acc[3][3] += av.w * bv.w;
        }
        __syncthreads();
    }

    const float4 bb = *(const float4*)&bias[n0 + (tx << 2)];
#pragma unroll
    for (int i = 0; i < 4; i++) {
        float4 outv;
        outv.x = acc[i][0] + bb.x;
        outv.y = acc[i][1] + bb.y;
        outv.z = acc[i][2] + bb.z;
        outv.w = acc[i][3] + bb.w;
        *(float4*)&C[(size_t)(m0 + (ty << 2) + i) * N + n0 + (tx << 2)] = outv;
    }
}

// ---------------------------------------------------------------------------
// Flash attention (no 1/sqrt(dh) scaling, per reference).
// Grid: (S/64, H, B). Block: 256 threads. BQ = BKV = 64, Dh = 64.
// Dynamic smem: Qt[64][64] (d-major), Kt[64][64] (d-major), Vs[64][64], Ss[64][64],
// plus per-row stats.
// ---------------------------------------------------------------------------
#define ATTN_SMEM_FLOATS (4 * 64 * 64 + 3 * 64)
#define ATTN_SMEM_BYTES  (ATTN_SMEM_FLOATS * 4)

__global__ __launch_bounds__(256) void attn_kernel(
    const float* __restrict__ Q, const float* __restrict__ K,
    const float* __restrict__ V, float* __restrict__ ctx)
{
    extern __shared__ float sm[];
    float* Qt = sm;                  // [d][q]   64*64
    float* Kt = sm + 4096;           // [d][kv]  64*64
    float* Vs = sm + 8192;           // [kv][d]  64*64
    float* Ss = sm + 12288;          // [q][kv]  64*64
    float* m_s    = sm + 16384;      // [64]
    float* l_s    = m_s + 64;        // [64]
    float* corr_s = l_s + 64;        // [64]

    const int tid  = threadIdx.x;
    const int tx   = tid & 15;       // kv/d column quad
    const int ty   = tid >> 4;       // q row quad
    const int lane = tid & 31;
    const int warp = tid >> 5;

    const int q0 = blockIdx.x * 64;
    const int h  = blockIdx.y;
    const int b  = blockIdx.z;
    const size_t base = (size_t)b * S_LEN * D_MODEL + (size_t)h * DHEAD;
    const float* qp = Q + base;
    const float* kp = K + base;
    const float* vp = V + base;

    // Load Q tile transposed into smem: Qt[d][row]
    {
        const int row = tid >> 2;           // 0..63
        const int dg  = (tid & 3) << 4;     // 0,16,32,48
#pragma unroll
        for (int ii = 0; ii < 4; ii++) {
            float4 v4 = *(const float4*)&qp[(size_t)(q0 + row) * D_MODEL + dg + ii * 4];
            Qt[(dg + ii * 4 + 0) * 64 + row] = v4.x;
            Qt[(dg + ii * 4 + 1) * 64 + row] = v4.y;
            Qt[(dg + ii * 4 + 2) * 64 + row] = v4.z;
            Qt[(dg + ii * 4 + 3) * 64 + row] = v4.w;
        }
    }
    if (tid < 64) { m_s[tid] = -3.0e38f; l_s[tid] = 0.0f; }

    float o[4][4] = {};
    __syncthreads();

    for (int kt = 0; kt < S_LEN; kt += 64) {
        // Load K (transposed) and V (natural) tiles
        {
            const int row = tid >> 2;
            const int dg  = (tid & 3) << 4;
#pragma unroll
            for (int ii = 0; ii < 4; ii++) {
                float4 k4 = *(const float4*)&kp[(size_t)(kt + row) * D_MODEL + dg + ii * 4];
                Kt[(dg + ii * 4 + 0) * 64 + row] = k4.x;
                Kt[(dg + ii * 4 + 1) * 64 + row] = k4.y;
                Kt[(dg + ii * 4 + 2) * 64 + row] = k4.z;
                Kt[(dg + ii * 4 + 3) * 64 + row] = k4.w;
                float4 v4 = *(const float4*)&vp[(size_t)(kt + row) * D_MODEL + dg + ii * 4];
                *(float4*)&Vs[row * 64 + dg + ii * 4] = v4;
            }
        }
        __syncthreads();

        // S = Q @ K^T  (64x64), thread computes 4x4
        float s[4][4] = {};
#pragma unroll 8
        for (int d = 0; d < 64; d++) {
            float4 qv = *(const float4*)&Qt[d * 64 + (ty << 2)];
            float4 kv = *(const float4*)&Kt[d * 64 + (tx << 2)];
            s[0][0] += qv.x * kv.x; s[0][1] += qv.x * kv.y;
            s[0][2] += qv.x * kv.z; s[0][3] += qv.x * kv.w;
            s[1][0] += qv.y * kv.x; s[1][1] += qv.y * kv.y;
            s[1][2] += qv.y * kv.z; s[1][3] += qv.y * kv.w;
            s[2][0] += qv.z * kv.x; s[2][1] += qv.z * kv.y;
            s[2][2] += qv.z * kv.z; s[2][3] += qv.z * kv.w;
            s[3][0] += qv.w * kv.x; s[3][1] += qv.w * kv.y;
            s[3][2] += qv.w * kv.z; s[3][3] += qv.w * kv.w;
        }
#pragma unroll
        for (int i = 0; i < 4; i++) {
            float4 sv = make_float4(s[i][0], s[i][1], s[i][2], s[i][3]);
            *(float4*)&Ss[((ty << 2) + i) * 64 + (tx << 2)] = sv;
        }
        __syncthreads();

        // Online softmax: each warp owns 8 rows; lanes cover 64 cols (2 each)
#pragma unroll
        for (int rr = 0; rr < 8; rr++) {
            const int r = warp * 8 + rr;
            float v0 = Ss[r * 64 + lane];
            float v1 = Ss[r * 64 + 32 + lane];
            float mx = fmaxf(v0, v1);
#pragma unroll
            for (int off = 16; off; off >>= 1)
                mx = fmaxf(mx, __shfl_xor_sync(0xffffffffu, mx, off));
            const float m_old = m_s[r];
            const float m_new = fmaxf(m_old, mx);
            const float p0 = __expf(v0 - m_new);
            const float p1 = __expf(v1 - m_new);
            Ss[r * 64 + lane]      = p0;
            Ss[r * 64 + 32 + lane] = p1;
            float ps = p0 + p1;
#pragma unroll
            for (int off = 16; off; off >>= 1)
                ps += __shfl_xor_sync(0xffffffffu, ps, off);
            if (lane == 0) {
                const float corr = __expf(m_old - m_new);
                corr_s[r] = corr;
                m_s[r]    = m_new;
                l_s[r]    = l_s[r] * corr + ps;
            }
        }
        __syncthreads();

        // Rescale accumulators, then O += P @ V
        float c0 = corr_s[(ty << 2) + 0];
        float c1 = corr_s[(ty << 2) + 1];
        float c2 = corr_s[(ty << 2) + 2];
        float c3 = corr_s[(ty << 2) + 3];
#pragma unroll
        for (int j = 0; j < 4; j++) {
            o[0][j] *= c0; o[1][j] *= c1; o[2][j] *= c2; o[3][j] *= c3;
        }
#pragma unroll 8
        for (int k2 = 0; k2 < 64; k2++) {
            float4 vv = *(const float4*)&Vs[k2 * 64 + (tx << 2)];
            const float p0 = Ss[((ty << 2) + 0) * 64 + k2];
            const float p1 = Ss[((ty << 2) + 1) * 64 + k2];
            const float p2 = Ss[((ty << 2) + 2) * 64 + k2];
            const float p3 = Ss[((ty << 2) + 3) * 64 + k2];
            o[0][0] += p0 * vv.x; o[0][1] += p0 * vv.y; o[0][2] += p0 * vv.z; o[0][3] += p0 * vv.w;
            o[1][0] += p1 * vv.x; o[1][1] += p1 * vv.y; o[1][2] += p1 * vv.z; o[1][3] += p1 * vv.w;
            o[2][0] += p2 * vv.x; o[2][1] += p2 * vv.y; o[2][2] += p2 * vv.z; o[2][3] += p2 * vv.w;
            o[3][0] += p3 * vv.x; o[3][1] += p3 * vv.y; o[3][2] += p3 * vv.z; o[3][3] += p3 * vv.w;
        }
        __syncthreads();
    }

    // Epilogue: divide by l, write ctx in [B, S, H*Dh] layout
#pragma unroll
    for (int i = 0; i < 4; i++) {
        const int r = (ty << 2) + i;
        const float inv = 1.0f / l_s[r];
        float4 outv = make_float4(o[i][0] * inv, o[i][1] * inv,
                                  o[i][2] * inv, o[i][3] * inv);
        *(float4*)&ctx[base + (size_t)(q0 + r) * D_MODEL + (tx << 2)] = outv;
    }
}

// ---------------------------------------------------------------------------
// Launch
// ---------------------------------------------------------------------------
extern "C" void kernel_launch(void* const* d_in, const int* in_sizes, int n_in,
                              void* d_out, int out_size)
{
    const float* x  = (const float*)d_in[0];
    const float* Wq = (const float*)d_in[1];
    const float* bq = (const float*)d_in[2];
    const float* Wk = (const float*)d_in[3];
    const float* bk = (const float*)d_in[4];
    const float* Wv = (const float*)d_in[5];
    const float* bv = (const float*)d_in[6];
    const float* Wo = (const float*)d_in[7];
    const float* bo = (const float*)d_in[8];
    float* out = (float*)d_out;

    float *q, *k, *v, *ctx;
    cudaGetSymbolAddress((void**)&q,   g_q);
    cudaGetSymbolAddress((void**)&k,   g_k);
    cudaGetSymbolAddress((void**)&v,   g_v);
    cudaGetSymbolAddress((void**)&ctx, g_ctx);

    cudaFuncSetAttribute(attn_kernel,
                         cudaFuncAttributeMaxDynamicSharedMemorySize,
                         ATTN_SMEM_BYTES);

    const dim3 ggrid(MROWS / BM, D_MODEL / BN);   // 64 x 12

    gemm_bias_kernel<<<ggrid, 256>>>(x, Wq, bq, q, MROWS, D_MODEL, D_MODEL);
    gemm_bias_kernel<<<ggrid, 256>>>(x, Wk, bk, k, MROWS, D_MODEL, D_MODEL);
    gemm_bias_kernel<<<ggrid, 256>>>(x, Wv, bv, v, MROWS, D_MODEL, D_MODEL);

    attn_kernel<<<dim3(S_LEN / 64, NH, BATCH), 256, ATTN_SMEM_BYTES>>>(q, k, v, ctx);

    gemm_bias_kernel<<<ggrid, 256>>>(ctx, Wo, bo, out, MROWS, D_MODEL, D_MODEL);
}

// round 12
// speedup vs baseline: 1.0611x; 1.0611x over previous
#include <cuda_runtime.h>
#include <math.h>
#include <stdint.h>

// Problem constants
#define S_LEN   2048
#define D_MODEL 768
#define NH      12
#define DHEAD   64
#define BATCH   2
#define MROWS   (BATCH * S_LEN)   // 4096

// ---------------------------------------------------------------------------
// Device scratch (no allocations allowed)
// ---------------------------------------------------------------------------
__device__ float g_q[MROWS * D_MODEL];
__device__ float g_k[MROWS * D_MODEL];
__device__ float g_v[MROWS * D_MODEL];
__device__ float g_ctx[MROWS * D_MODEL];
__device__ float g_wt[4][D_MODEL * D_MODEL];   // transposed weights [N][K]

// ---------------------------------------------------------------------------
// tf32 split helper: v -> (hi, lo) as tf32-valued b32 registers
// ---------------------------------------------------------------------------
__device__ __forceinline__ void split2(float v, uint32_t& hi, uint32_t& lo) {
    uint32_t h;
    asm("cvt.rna.tf32.f32 %0, %1;" : "=r"(h) : "f"(v));
    float rem = v - __uint_as_float(h);
    uint32_t l;
    asm("cvt.rna.tf32.f32 %0, %1;" : "=r"(l) : "f"(rem));
    hi = h; lo = l;
}

__device__ __forceinline__ void mma_tf32(float* c, const uint32_t* a, const uint32_t* b) {
    asm volatile(
        "mma.sync.aligned.m16n8k8.row.col.f32.tf32.tf32.f32 "
        "{%0,%1,%2,%3}, {%4,%5,%6,%7}, {%8,%9}, {%0,%1,%2,%3};"
        : "+f"(c[0]), "+f"(c[1]), "+f"(c[2]), "+f"(c[3])
        : "r"(a[0]), "r"(a[1]), "r"(a[2]), "r"(a[3]), "r"(b[0]), "r"(b[1]));
}

// ---------------------------------------------------------------------------
// Weight transpose: W[K][N] row-major -> Wt[N][K]
// ---------------------------------------------------------------------------
__global__ void transpose_kernel(const float* __restrict__ W, float* __restrict__ Wt)
{
    __shared__ float t[32][33];
    const int bx = blockIdx.x * 32;   // n
    const int by = blockIdx.y * 32;   // k
    const int tx = threadIdx.x, ty = threadIdx.y;
#pragma unroll
    for (int i = 0; i < 4; i++)
        t[ty + i * 8][tx] = W[(size_t)(by + ty + i * 8) * D_MODEL + bx + tx];
    __syncthreads();
#pragma unroll
    for (int i = 0; i < 4; i++)
        Wt[(size_t)(bx + ty + i * 8) * D_MODEL + by + tx] = t[tx][ty + i * 8];
}

// ---------------------------------------------------------------------------
// 3xTF32 mma.sync GEMM: C[M,N] = A[M,K] @ Wt[N,K]^T + bias
// CTA tile 128x128, BK=32, double-buffered smem, 256 threads (8 warps 2m x 4n)
// Warp tile 64x32: 4 m16 tiles x 4 n8 tiles.
// ---------------------------------------------------------------------------
#define BK      32
#define LDA     36                   // padded row stride (words) -> conflict-free frags
#define NKT     (D_MODEL / BK)       // 24
#define TILE_WORDS (128 * LDA)       // per buffer
#define GEMM_SMEM  (4 * TILE_WORDS * 4)   // A(2) + B(2) buffers = 73728 B

__global__ __launch_bounds__(256) void gemm_mma(
    const float* __restrict__ A, const float* __restrict__ Bt,
    const float* __restrict__ bias, float* __restrict__ C)
{
    extern __shared__ float sm[];
    float* As = sm;                       // [2][128][LDA]
    float* Bs = sm + 2 * TILE_WORDS;      // [2][128][LDA]
    __shared__ float bias_s[128];

    const int tid  = threadIdx.x;
    const int lane = tid & 31;
    const int wid  = tid >> 5;
    const int warp_m = wid & 1;           // 0..1 (64 rows each)
    const int warp_n = wid >> 1;          // 0..3 (32 cols each)

    const int m0 = blockIdx.x * 128;
    const int n0 = blockIdx.y * 128;

    if (tid < 128) bias_s[tid] = bias[n0 + tid];

    // global load mapping: 128 rows x 32 cols per tile; thread -> 16 floats
    const int lrow = tid >> 1;            // 0..127
    const int lcol = (tid & 1) * 16;      // 0 or 16

    const float* aptr = A  + (size_t)(m0 + lrow) * D_MODEL + lcol;
    const float* bptr = Bt + (size_t)(n0 + lrow) * D_MODEL + lcol;

    float4 ra[4], rb[4];
#pragma unroll
    for (int j = 0; j < 4; j++) {
        ra[j] = *(const float4*)(aptr + j * 4);
        rb[j] = *(const float4*)(bptr + j * 4);
    }

    float acc[4][4][4] = {};    // [mt][nt][4]

    int buf = 0;
    {
        float* Ad = As + buf * TILE_WORDS + lrow * LDA + lcol;
        float* Bd = Bs + buf * TILE_WORDS + lrow * LDA + lcol;
#pragma unroll
        for (int j = 0; j < 4; j++) {
            *(float4*)(Ad + j * 4) = ra[j];
            *(float4*)(Bd + j * 4) = rb[j];
        }
    }
    __syncthreads();

    for (int c = 0; c < NKT; c++) {
        // prefetch next chunk
        if (c + 1 < NKT) {
#pragma unroll
            for (int j = 0; j < 4; j++) {
                ra[j] = *(const float4*)(aptr + (c + 1) * BK + j * 4);
                rb[j] = *(const float4*)(bptr + (c + 1) * BK + j * 4);
            }
        }

        const float* Ab = As + buf * TILE_WORDS;
        const float* Bb = Bs + buf * TILE_WORDS;

#pragma unroll
        for (int ks = 0; ks < 4; ks++) {
            const int k0 = ks * 8;
            // A fragments for 4 m16 tiles, split to tf32 hi/lo
            uint32_t ah[4][4], al[4][4];
#pragma unroll
            for (int mt = 0; mt < 4; mt++) {
                const int r = warp_m * 64 + mt * 16 + (lane >> 2);
                const int kc = k0 + (lane & 3);
                split2(Ab[(r)     * LDA + kc],     ah[mt][0], al[mt][0]);
                split2(Ab[(r + 8) * LDA + kc],     ah[mt][1], al[mt][1]);
                split2(Ab[(r)     * LDA + kc + 4], ah[mt][2], al[mt][2]);
                split2(Ab[(r + 8) * LDA + kc + 4], ah[mt][3], al[mt][3]);
            }
            // B fragments for 4 n8 tiles
            uint32_t bh[4][2], bl[4][2];
#pragma unroll
            for (int nt = 0; nt < 4; nt++) {
                const int r = warp_n * 32 + nt * 8 + (lane >> 2);
                const int kc = k0 + (lane & 3);
                split2(Bb[r * LDA + kc],     bh[nt][0], bl[nt][0]);
                split2(Bb[r * LDA + kc + 4], bh[nt][1], bl[nt][1]);
            }
#pragma unroll
            for (int mt = 0; mt < 4; mt++) {
#pragma unroll
                for (int nt = 0; nt < 4; nt++) {
                    mma_tf32(acc[mt][nt], ah[mt], bh[nt]);
                    mma_tf32(acc[mt][nt], ah[mt], bl[nt]);
                    mma_tf32(acc[mt][nt], al[mt], bh[nt]);
                }
            }
        }

        // store prefetched chunk into other buffer
        if (c + 1 < NKT) {
            float* Ad = As + (buf ^ 1) * TILE_WORDS + lrow * LDA + lcol;
            float* Bd = Bs + (buf ^ 1) * TILE_WORDS + lrow * LDA + lcol;
#pragma unroll
            for (int j = 0; j < 4; j++) {
                *(float4*)(Ad + j * 4) = ra[j];
                *(float4*)(Bd + j * 4) = rb[j];
            }
            __syncthreads();
            buf ^= 1;
        }
    }

    // Epilogue: write accumulators + bias
#pragma unroll
    for (int mt = 0; mt < 4; mt++) {
        const int mrow = m0 + warp_m * 64 + mt * 16 + (lane >> 2);
#pragma unroll
        for (int nt = 0; nt < 4; nt++) {
            const int ncol = warp_n * 32 + nt * 8 + (lane & 3) * 2;
            float2 o0, o1;
            o0.x = acc[mt][nt][0] + bias_s[ncol];
            o0.y = acc[mt][nt][1] + bias_s[ncol + 1];
            o1.x = acc[mt][nt][2] + bias_s[ncol];
            o1.y = acc[mt][nt][3] + bias_s[ncol + 1];
            *(float2*)&C[(size_t)(mrow)     * D_MODEL + n0 + ncol] = o0;
            *(float2*)&C[(size_t)(mrow + 8) * D_MODEL + n0 + ncol] = o1;
        }
    }
}

// ---------------------------------------------------------------------------
// Flash attention (fp32 SIMT, unchanged from passing round-2 kernel)
// ---------------------------------------------------------------------------
#define ATTN_SMEM_FLOATS (4 * 64 * 64 + 3 * 64)
#define ATTN_SMEM_BYTES  (ATTN_SMEM_FLOATS * 4)

__global__ __launch_bounds__(256) void attn_kernel(
    const float* __restrict__ Q, const float* __restrict__ K,
    const float* __restrict__ V, float* __restrict__ ctx)
{
    extern __shared__ float sm[];
    float* Qt = sm;
    float* Kt = sm + 4096;
    float* Vs = sm + 8192;
    float* Ss = sm + 12288;
    float* m_s    = sm + 16384;
    float* l_s    = m_s + 64;
    float* corr_s = l_s + 64;

    const int tid  = threadIdx.x;
    const int tx   = tid & 15;
    const int ty   = tid >> 4;
    const int lane = tid & 31;
    const int warp = tid >> 5;

    const int q0 = blockIdx.x * 64;
    const int h  = blockIdx.y;
    const int b  = blockIdx.z;
    const size_t base = (size_t)b * S_LEN * D_MODEL + (size_t)h * DHEAD;
    const float* qp = Q + base;
    const float* kp = K + base;
    const float* vp = V + base;

    {
        const int row = tid >> 2;
        const int dg  = (tid & 3) << 4;
#pragma unroll
        for (int ii = 0; ii < 4; ii++) {
            float4 v4 = *(const float4*)&qp[(size_t)(q0 + row) * D_MODEL + dg + ii * 4];
            Qt[(dg + ii * 4 + 0) * 64 + row] = v4.x;
            Qt[(dg + ii * 4 + 1) * 64 + row] = v4.y;
            Qt[(dg + ii * 4 + 2) * 64 + row] = v4.z;
            Qt[(dg + ii * 4 + 3) * 64 + row] = v4.w;
        }
    }
    if (tid < 64) { m_s[tid] = -3.0e38f; l_s[tid] = 0.0f; }

    float o[4][4] = {};
    __syncthreads();

    for (int kt = 0; kt < S_LEN; kt += 64) {
        {
            const int row = tid >> 2;
            const int dg  = (tid & 3) << 4;
#pragma unroll
            for (int ii = 0; ii < 4; ii++) {
                float4 k4 = *(const float4*)&kp[(size_t)(kt + row) * D_MODEL + dg + ii * 4];
                Kt[(dg + ii * 4 + 0) * 64 + row] = k4.x;
                Kt[(dg + ii * 4 + 1) * 64 + row] = k4.y;
                Kt[(dg + ii * 4 + 2) * 64 + row] = k4.z;
                Kt[(dg + ii * 4 + 3) * 64 + row] = k4.w;
                float4 v4 = *(const float4*)&vp[(size_t)(kt + row) * D_MODEL + dg + ii * 4];
                *(float4*)&Vs[row * 64 + dg + ii * 4] = v4;
            }
        }
        __syncthreads();

        float s[4][4] = {};
#pragma unroll 8
        for (int d = 0; d < 64; d++) {
            float4 qv = *(const float4*)&Qt[d * 64 + (ty << 2)];
            float4 kv = *(const float4*)&Kt[d * 64 + (tx << 2)];
            s[0][0] += qv.x * kv.x; s[0][1] += qv.x * kv.y;
            s[0][2] += qv.x * kv.z; s[0][3] += qv.x * kv.w;
            s[1][0] += qv.y * kv.x; s[1][1] += qv.y * kv.y;
            s[1][2] += qv.y * kv.z; s[1][3] += qv.y * kv.w;
            s[2][0] += qv.z * kv.x; s[2][1] += qv.z * kv.y;
            s[2][2] += qv.z * kv.z; s[2][3] += qv.z * kv.w;
            s[3][0] += qv.w * kv.x; s[3][1] += qv.w * kv.y;
            s[3][2] += qv.w * kv.z; s[3][3] += qv.w * kv.w;
        }
#pragma unroll
        for (int i = 0; i < 4; i++) {
            float4 sv = make_float4(s[i][0], s[i][1], s[i][2], s[i][3]);
            *(float4*)&Ss[((ty << 2) + i) * 64 + (tx << 2)] = sv;
        }
        __syncthreads();

#pragma unroll
        for (int rr = 0; rr < 8; rr++) {
            const int rix = warp * 8 + rr;
            float v0 = Ss[rix * 64 + lane];
            float v1 = Ss[rix * 64 + 32 + lane];
            float mx = fmaxf(v0, v1);
#pragma unroll
            for (int off = 16; off; off >>= 1)
                mx = fmaxf(mx, __shfl_xor_sync(0xffffffffu, mx, off));
            const float m_old = m_s[rix];
            const float m_new = fmaxf(m_old, mx);
            const float p0 = __expf(v0 - m_new);
            const float p1 = __expf(v1 - m_new);
            Ss[rix * 64 + lane]      = p0;
            Ss[rix * 64 + 32 + lane] = p1;
            float ps = p0 + p1;
#pragma unroll
            for (int off = 16; off; off >>= 1)
                ps += __shfl_xor_sync(0xffffffffu, ps, off);
            if (lane == 0) {
                const float corr = __expf(m_old - m_new);
                corr_s[rix] = corr;
                m_s[rix]    = m_new;
                l_s[rix]    = l_s[rix] * corr + ps;
            }
        }
        __syncthreads();

        float c0 = corr_s[(ty << 2) + 0];
        float c1 = corr_s[(ty << 2) + 1];
        float c2 = corr_s[(ty << 2) + 2];
        float c3 = corr_s[(ty << 2) + 3];
#pragma unroll
        for (int j = 0; j < 4; j++) {
            o[0][j] *= c0; o[1][j] *= c1; o[2][j] *= c2; o[3][j] *= c3;
        }
#pragma unroll 8
        for (int k2 = 0; k2 < 64; k2++) {
            float4 vv = *(const float4*)&Vs[k2 * 64 + (tx << 2)];
            const float p0 = Ss[((ty << 2) + 0) * 64 + k2];
            const float p1 = Ss[((ty << 2) + 1) * 64 + k2];
            const float p2 = Ss[((ty << 2) + 2) * 64 + k2];
            const float p3 = Ss[((ty << 2) + 3) * 64 + k2];
            o[0][0] += p0 * vv.x; o[0][1] += p0 * vv.y; o[0][2] += p0 * vv.z; o[0][3] += p0 * vv.w;
            o[1][0] += p1 * vv.x; o[1][1] += p1 * vv.y; o[1][2] += p1 * vv.z; o[1][3] += p1 * vv.w;
            o[2][0] += p2 * vv.x; o[2][1] += p2 * vv.y; o[2][2] += p2 * vv.z; o[2][3] += p2 * vv.w;
            o[3][0] += p3 * vv.x; o[3][1] += p3 * vv.y; o[3][2] += p3 * vv.z; o[3][3] += p3 * vv.w;
        }
        __syncthreads();
    }

#pragma unroll
    for (int i = 0; i < 4; i++) {
        const int rix = (ty << 2) + i;
        const float inv = 1.0f / l_s[rix];
        float4 outv = make_float4(o[i][0] * inv, o[i][1] * inv,
                                  o[i][2] * inv, o[i][3] * inv);
        *(float4*)&ctx[base + (size_t)(q0 + rix) * D_MODEL + (tx << 2)] = outv;
    }
}

// ---------------------------------------------------------------------------
// Launch
// ---------------------------------------------------------------------------
extern "C" void kernel_launch(void* const* d_in, const int* in_sizes, int n_in,
                              void* d_out, int out_size)
{
    const float* x  = (const float*)d_in[0];
    const float* Wq = (const float*)d_in[1];
    const float* bq = (const float*)d_in[2];
    const float* Wk = (const float*)d_in[3];
    const float* bk = (const float*)d_in[4];
    const float* Wv = (const float*)d_in[5];
    const float* bv = (const float*)d_in[6];
    const float* Wo = (const float*)d_in[7];
    const float* bo = (const float*)d_in[8];
    float* out = (float*)d_out;

    float *q, *k, *v, *ctx, *wt;
    cudaGetSymbolAddress((void**)&q,   g_q);
    cudaGetSymbolAddress((void**)&k,   g_k);
    cudaGetSymbolAddress((void**)&v,   g_v);
    cudaGetSymbolAddress((void**)&ctx, g_ctx);
    cudaGetSymbolAddress((void**)&wt,  g_wt);

    cudaFuncSetAttribute(attn_kernel,
                         cudaFuncAttributeMaxDynamicSharedMemorySize,
                         ATTN_SMEM_BYTES);
    cudaFuncSetAttribute(gemm_mma,
                         cudaFuncAttributeMaxDynamicSharedMemorySize,
                         GEMM_SMEM);

    const int WELEM = D_MODEL * D_MODEL;

    transpose_kernel<<<dim3(24, 24), dim3(32, 8)>>>(Wq, wt + 0 * WELEM);
    transpose_kernel<<<dim3(24, 24), dim3(32, 8)>>>(Wk, wt + 1 * WELEM);
    transpose_kernel<<<dim3(24, 24), dim3(32, 8)>>>(Wv, wt + 2 * WELEM);
    transpose_kernel<<<dim3(24, 24), dim3(32, 8)>>>(Wo, wt + 3 * WELEM);

    const dim3 ggrid(MROWS / 128, D_MODEL / 128);   // 32 x 6

    gemm_mma<<<ggrid, 256, GEMM_SMEM>>>(x, wt + 0 * WELEM, bq, q);
    gemm_mma<<<ggrid, 256, GEMM_SMEM>>>(x, wt + 1 * WELEM, bk, k);
    gemm_mma<<<ggrid, 256, GEMM_SMEM>>>(x, wt + 2 * WELEM, bv, v);

    attn_kernel<<<dim3(S_LEN / 64, NH, BATCH), 256, ATTN_SMEM_BYTES>>>(q, k, v, ctx);

    gemm_mma<<<ggrid, 256, GEMM_SMEM>>>(ctx, wt + 3 * WELEM, bo, out);
}